// round 1
// baseline (speedup 1.0000x reference)
#include <cuda_runtime.h>
#include <mma.h>
#include <cstdint>

using namespace nvcuda;

#define D 128
#define MT 64          // rows per tile
#define LDX 132        // smem stride (floats) for xd tile (pad vs bank conflicts)
#define LDW 132        // smem stride (floats) for W'
#define NTHREADS 256
#define GRID 304       // 2 CTAs/SM * 152 SMs (GB300)

// Scratch for W' = W @ S (allocation-free per harness rules)
__device__ __align__(16) float g_wprime[D * D];

// ---------------------------------------------------------------------------
// Kernel 1: W' = W @ S, fp32 exact. 128 blocks x 128 threads. Trivial cost.
// ---------------------------------------------------------------------------
__global__ void wprime_kernel(const float* __restrict__ W, const float* __restrict__ S) {
    __shared__ float wrow[D];
    const int i = blockIdx.x;
    const int j = threadIdx.x;
    wrow[j] = W[i * D + j];
    __syncthreads();
    float acc = 0.f;
#pragma unroll
    for (int k = 0; k < D; ++k) acc = fmaf(wrow[k], S[k * D + j], acc);
    g_wprime[i * D + j] = acc;
}

// ---------------------------------------------------------------------------
// Kernel 2: out = relu((x .* mask) @ W')   [N x 128] @ [128 x 128]
// Persistent CTAs, 64-row tiles, TF32 wmma, register-staged pipeline.
// ---------------------------------------------------------------------------
__global__ __launch_bounds__(NTHREADS, 2) void gcn_kernel(
    const float* __restrict__ x, const float* __restrict__ mask,
    float* __restrict__ out, int nrows, int ntiles)
{
    extern __shared__ float smem[];
    float* ws = smem;              // D * LDW floats   (W')
    float* xb = ws + D * LDW;      // MT * LDX floats  (xd tile)

    // Load W' (L2-resident) into smem, padded stride
    for (int i = threadIdx.x; i < (D * D) / 4; i += NTHREADS) {
        int r = i >> 5, c4 = i & 31;
        float4 v = reinterpret_cast<const float4*>(g_wprime)[i];
        *reinterpret_cast<float4*>(&ws[r * LDW + c4 * 4]) = v;
    }

    const int wid = threadIdx.x >> 5;
    const int wr  = wid & 3;   // warp row group: rows [16*wr, 16*wr+16)
    const int wc  = wid >> 2;  // warp col group: cols [64*wc, 64*wc+64)

    // Register staging: 8 float4 of x + 8 of mask per thread per tile
    float4 rx[8], rm[8];
    auto ldg_tile = [&](int tile) {
#pragma unroll
        for (int i = 0; i < 8; ++i) {
            int e = threadIdx.x + i * NTHREADS;   // 0..2047
            int row = e >> 5, c4 = e & 31;
            int r = tile * MT + row;
            if (r < nrows) {
                rx[i] = *reinterpret_cast<const float4*>(x    + (size_t)r * D + c4 * 4);
                rm[i] = *reinterpret_cast<const float4*>(mask + (size_t)r * D + c4 * 4);
            } else {
                rx[i] = make_float4(0.f, 0.f, 0.f, 0.f);
                rm[i] = make_float4(0.f, 0.f, 0.f, 0.f);
            }
        }
    };

    int t = blockIdx.x;
    if (t < ntiles) ldg_tile(t);
    __syncthreads();   // W' visible to all warps

    for (; t < ntiles; t += gridDim.x) {
        // Stage xd = x * mask into smem (fused multiply at STS)
#pragma unroll
        for (int i = 0; i < 8; ++i) {
            int e = threadIdx.x + i * NTHREADS;
            int row = e >> 5, c4 = e & 31;
            float4 v;
            v.x = rx[i].x * rm[i].x;  v.y = rx[i].y * rm[i].y;
            v.z = rx[i].z * rm[i].z;  v.w = rx[i].w * rm[i].w;
            *reinterpret_cast<float4*>(&xb[row * LDX + c4 * 4]) = v;
        }
        __syncthreads();

        // Prefetch next tile into registers; LDG latency hidden by MMA below
        int tn = t + gridDim.x;
        if (tn < ntiles) ldg_tile(tn);

        wmma::fragment<wmma::accumulator, 16, 16, 8, float> acc[4];
#pragma unroll
        for (int n = 0; n < 4; ++n) wmma::fill_fragment(acc[n], 0.f);

#pragma unroll
        for (int k = 0; k < 16; ++k) {
            wmma::fragment<wmma::matrix_a, 16, 16, 8, wmma::precision::tf32, wmma::row_major> a;
            wmma::load_matrix_sync(a, &xb[(wr * 16) * LDX + k * 8], LDX);
#pragma unroll
            for (int e = 0; e < a.num_elements; ++e) a.x[e] = wmma::__float_to_tf32(a.x[e]);
#pragma unroll
            for (int n = 0; n < 4; ++n) {
                wmma::fragment<wmma::matrix_b, 16, 16, 8, wmma::precision::tf32, wmma::row_major> b;
                wmma::load_matrix_sync(b, &ws[(k * 8) * LDW + wc * 64 + n * 16], LDW);
#pragma unroll
                for (int e = 0; e < b.num_elements; ++e) b.x[e] = wmma::__float_to_tf32(b.x[e]);
                wmma::mma_sync(acc[n], a, b, acc[n]);
            }
        }

        // ReLU on accumulators
#pragma unroll
        for (int n = 0; n < 4; ++n)
#pragma unroll
            for (int e = 0; e < acc[n].num_elements; ++e)
                acc[n].x[e] = fmaxf(acc[n].x[e], 0.f);

        const int rem = nrows - t * MT;
        if (rem >= MT) {
            float* obase = out + (size_t)t * MT * D + (wr * 16) * D + wc * 64;
#pragma unroll
            for (int n = 0; n < 4; ++n)
                wmma::store_matrix_sync(obase + n * 16, acc[n], D, wmma::mem_row_major);
        } else {
            // Partial tail tile (last tile only): stage in smem, guarded copy
            __syncthreads();
#pragma unroll
            for (int n = 0; n < 4; ++n)
                wmma::store_matrix_sync(&xb[(wr * 16) * LDX + wc * 64 + n * 16],
                                        acc[n], LDX, wmma::mem_row_major);
            __syncthreads();
            for (int e = threadIdx.x; e < rem * 32; e += NTHREADS) {
                int row = e >> 5, c4 = e & 31;
                float4 v = *reinterpret_cast<float4*>(&xb[row * LDX + c4 * 4]);
                *reinterpret_cast<float4*>(out + (size_t)(t * MT + row) * D + c4 * 4) = v;
            }
        }
        __syncthreads();
    }
}

// ---------------------------------------------------------------------------
// Harness entry
// ---------------------------------------------------------------------------
extern "C" void kernel_launch(void* const* d_in, const int* in_sizes, int n_in,
                              void* d_out, int out_size) {
    const float* x    = (const float*)d_in[0];   // [N, 128]
    const float* W    = (const float*)d_in[1];   // [128, 128]
    const float* S    = (const float*)d_in[2];   // [128, 128]
    const float* mask = (const float*)d_in[3];   // [N, 128]
    float* out = (float*)d_out;

    const int nrows  = in_sizes[0] / D;
    const int ntiles = (nrows + MT - 1) / MT;

    const size_t smem = (size_t)(D * LDW + MT * LDX) * sizeof(float);  // ~99 KB
    cudaFuncSetAttribute(gcn_kernel, cudaFuncAttributeMaxDynamicSharedMemorySize, (int)smem);

    wprime_kernel<<<D, D>>>(W, S);
    gcn_kernel<<<GRID, NTHREADS, smem>>>(x, mask, out, nrows, ntiles);
}

// round 4
// speedup vs baseline: 2.4517x; 2.4517x over previous
#include <cuda_runtime.h>
#include <cstdint>

#define D 128
#define MT 16          // rows per tile (500000 = 31250 * 16, tail guarded anyway)
#define LDX 132        // smem stride (floats): 132 mod 32 = 4 -> conflict-free ldmatrix rows
#define NTHREADS 256
#define GRID 304       // 2 CTAs/SM * 152 SMs

// Scratch for W' = W @ S, pre-rounded to tf32 (allocation-free per harness rules)
__device__ __align__(16) float g_wprime[D * D];

__device__ __forceinline__ float tf32_rna(float v) {
    uint32_t r;
    asm("cvt.rna.tf32.f32 %0, %1;" : "=r"(r) : "f"(v));
    return __uint_as_float(r);
}

__device__ __forceinline__ uint32_t smem_u32(const void* p) {
    return (uint32_t)__cvta_generic_to_shared(p);
}

// ---------------------------------------------------------------------------
// Kernel 1: W' = W @ S in exact fp32, then round once to tf32. Trivial cost.
// ---------------------------------------------------------------------------
__global__ void wprime_kernel(const float* __restrict__ W, const float* __restrict__ S) {
    __shared__ float wrow[D];
    const int i = blockIdx.x;
    const int j = threadIdx.x;
    wrow[j] = W[i * D + j];
    __syncthreads();
    float acc = 0.f;
#pragma unroll
    for (int k = 0; k < D; ++k) acc = fmaf(wrow[k], S[k * D + j], acc);
    g_wprime[i * D + j] = tf32_rna(acc);
}

// ---------------------------------------------------------------------------
// Kernel 2: out = relu((x .* mask) @ W')   [N x 128] @ [128 x 128]
// 8 warps/CTA; warp w owns output cols [16w, 16w+16) for all 16 tile rows.
// W' slice register-resident (64 regs/lane). xd tile double-buffered in smem,
// A fragments via ldmatrix.x4 (correct tf32 m16n8k8 layout).
// ---------------------------------------------------------------------------
__global__ __launch_bounds__(NTHREADS, 2) void gcn_kernel(
    const float* __restrict__ x, const float* __restrict__ mask,
    float* __restrict__ out, int nrows, int ntiles)
{
    __shared__ float xs[2][MT * LDX];

    const int tid  = threadIdx.x;
    const int wid  = tid >> 5;
    const int lane = tid & 31;
    const int g    = lane >> 2;  // 0..7
    const int tg   = lane & 3;   // 0..3

    // ---- Preload B fragments (K=128 x N=16 per warp) into registers, once ----
    // tf32 m16n8k8 B layout (col-major 8x8 block): b0 = B[tg][n], b1 = B[tg+4][n]
    uint32_t breg[16][2][2];
#pragma unroll
    for (int kb = 0; kb < 16; ++kb)
#pragma unroll
        for (int j = 0; j < 2; ++j) {
            const int col = wid * 16 + j * 8 + g;
            breg[kb][j][0] = __float_as_uint(g_wprime[(kb * 8 + tg    ) * D + col]);
            breg[kb][j][1] = __float_as_uint(g_wprime[(kb * 8 + tg + 4) * D + col]);
        }

    // ---- ldmatrix source address (per-lane), for each buffer ----
    // matrices: 0 = rows 0-7 / cols 0-3,  1 = rows 8-15 / cols 0-3,
    //           2 = rows 0-7 / cols 4-7,  3 = rows 8-15 / cols 4-7
    const int lrow  = (lane & 7) + ((lane >> 3) & 1) * 8;  // row 0..15
    const int lcoff = (lane >> 4) * 4;                     // col offset 0 or 4
    const uint32_t abase0 = smem_u32(&xs[0][lrow * LDX + lcoff]);
    const uint32_t abase1 = smem_u32(&xs[1][lrow * LDX + lcoff]);

    // ---- Register staging for x / mask (2 float4 each per thread per tile) ----
    float4 rx[2], rm[2];
    rx[0] = rx[1] = rm[0] = rm[1] = make_float4(0.f, 0.f, 0.f, 0.f);
    auto ldg_tile = [&](int tile) {
#pragma unroll
        for (int i = 0; i < 2; ++i) {
            const int e   = tid + i * NTHREADS;   // 0..511 = 16 rows x 32 float4
            const int row = e >> 5, c4 = e & 31;
            const int r   = tile * MT + row;
            if (r < nrows) {
                rx[i] = *reinterpret_cast<const float4*>(x    + (size_t)r * D + c4 * 4);
                rm[i] = *reinterpret_cast<const float4*>(mask + (size_t)r * D + c4 * 4);
            } else {
                rx[i] = make_float4(0.f, 0.f, 0.f, 0.f);
                rm[i] = rx[i];
            }
        }
    };

    int t = blockIdx.x;
    if (t < ntiles) ldg_tile(t);

    int p = 0;
    for (; t < ntiles; t += GRID, p ^= 1) {
        // ---- STS: xd = tf32_round(x * mask) into buffer p ----
        float* xbuf = xs[p];
#pragma unroll
        for (int i = 0; i < 2; ++i) {
            const int e   = tid + i * NTHREADS;
            const int row = e >> 5, c4 = e & 31;
            float4 v;
            v.x = tf32_rna(rx[i].x * rm[i].x);
            v.y = tf32_rna(rx[i].y * rm[i].y);
            v.z = tf32_rna(rx[i].z * rm[i].z);
            v.w = tf32_rna(rx[i].w * rm[i].w);
            *reinterpret_cast<float4*>(&xbuf[row * LDX + c4 * 4]) = v;
        }
        __syncthreads();

        // ---- Prefetch next tile into registers (latency hidden by MMAs) ----
        const int tn = t + GRID;
        if (tn < ntiles) ldg_tile(tn);

        // ---- MMA: 16 k-blocks x 2 n-blocks of m16n8k8 tf32 ----
        float acc[2][4] = {{0.f,0.f,0.f,0.f},{0.f,0.f,0.f,0.f}};
        const uint32_t abase = p ? abase1 : abase0;
#pragma unroll
        for (int kb = 0; kb < 16; ++kb) {
            uint32_t a0, a1, a2, a3;
            asm volatile(
                "ldmatrix.sync.aligned.m8n8.x4.shared.b16 {%0,%1,%2,%3}, [%4];"
                : "=r"(a0), "=r"(a1), "=r"(a2), "=r"(a3)
                : "r"(abase + kb * 32));
#pragma unroll
            for (int j = 0; j < 2; ++j) {
                asm volatile(
                    "mma.sync.aligned.m16n8k8.row.col.f32.tf32.tf32.f32 "
                    "{%0,%1,%2,%3}, {%4,%5,%6,%7}, {%8,%9}, {%0,%1,%2,%3};"
                    : "+f"(acc[j][0]), "+f"(acc[j][1]), "+f"(acc[j][2]), "+f"(acc[j][3])
                    : "r"(a0), "r"(a1), "r"(a2), "r"(a3),
                      "r"(breg[kb][j][0]), "r"(breg[kb][j][1]));
            }
        }

        // ---- Epilogue: ReLU + STG.64 (C layout: rows g/g+8, cols 2tg,2tg+1) ----
        const int r0 = t * MT + g;
        const int r1 = r0 + 8;
#pragma unroll
        for (int j = 0; j < 2; ++j) {
            const int c = wid * 16 + j * 8 + 2 * tg;
            if (r0 < nrows) {
                float2 v; v.x = fmaxf(acc[j][0], 0.f); v.y = fmaxf(acc[j][1], 0.f);
                *reinterpret_cast<float2*>(out + (size_t)r0 * D + c) = v;
            }
            if (r1 < nrows) {
                float2 v; v.x = fmaxf(acc[j][2], 0.f); v.y = fmaxf(acc[j][3], 0.f);
                *reinterpret_cast<float2*>(out + (size_t)r1 * D + c) = v;
            }
        }
        // No trailing barrier: next STS targets the other buffer, whose last
        // readers (this iteration's ldmatrix) completed before the next
        // iteration's __syncthreads() releases the STS of that buffer.
    }
}

// ---------------------------------------------------------------------------
// Harness entry
// ---------------------------------------------------------------------------
extern "C" void kernel_launch(void* const* d_in, const int* in_sizes, int n_in,
                              void* d_out, int out_size) {
    const float* x    = (const float*)d_in[0];   // [N, 128]
    const float* W    = (const float*)d_in[1];   // [128, 128]
    const float* S    = (const float*)d_in[2];   // [128, 128]
    const float* mask = (const float*)d_in[3];   // [N, 128]
    float* out = (float*)d_out;

    const int nrows  = in_sizes[0] / D;
    const int ntiles = (nrows + MT - 1) / MT;

    wprime_kernel<<<D, D>>>(W, S);
    gcn_kernel<<<GRID, NTHREADS>>>(x, mask, out, nrows, ntiles);
}